// round 4
// baseline (speedup 1.0000x reference)
#include <cuda_runtime.h>

#define HH 512
#define WW 512
#define BB 32
#define TILE 64
#define GDIM 70       // TILE + 6 (halo 3/side: 2 gaussian + 1 laplacian)
#define GSTRIDE 71
#define BDIM 66       // TILE + 2 (laplacian halo on blur)
#define HSTRIDE 67
#define NPIX (BB * HH * WW)        // 8388608 per image
#define RED_BLOCKS 2048

__device__ float g_edges[2 * NPIX];      // [img][b][h][w] edge maps (64 MB scratch)
__device__ float g_partials[RED_BLOCKS];

// ---------------------------------------------------------------------------
// Kernel 1: per-(img,b) 64x64 tile -> edge map |laplacian(gaussian(gray((x+1)/2)))|
// ---------------------------------------------------------------------------
__global__ __launch_bounds__(256)
void edge_map_kernel(const float* __restrict__ gen, const float* __restrict__ real_) {
    __shared__ float sA[GDIM * GSTRIDE];   // gray tile, later reused for blur
    __shared__ float sH[GDIM * HSTRIDE];   // horizontal-blur intermediate

    const int tid = threadIdx.x;
    const int ox  = blockIdx.x * TILE;
    const int oy  = blockIdx.y * TILE;
    const int img = blockIdx.z >> 5;   // 0 = generated, 1 = real
    const int b   = blockIdx.z & 31;

    // 5-tap gaussian (sigma=1), normalized (matches jnp fp32 within 1e-8)
    const float w0 = 0.054488685f;
    const float w1 = 0.244201342f;
    const float w2 = 0.402619947f;

    const float* src = img ? real_ : gen;
    const float* Rp = src + (size_t)b * 3 * HH * WW;
    const float* Gp = Rp + HH * WW;
    const float* Bp = Gp + HH * WW;

    // 1) grayscale of (x+1)/2 with 3-px halo; zero outside image
    for (int l = tid; l < GDIM * GDIM; l += 256) {
        int i = l / GDIM, j = l - i * GDIM;
        int gy = oy - 3 + i;
        int gx = ox - 3 + j;
        float v = 0.0f;
        if (gy >= 0 && gy < HH && gx >= 0 && gx < WW) {
            int idx = gy * WW + gx;
            float d = 0.299f * Rp[idx] + 0.587f * Gp[idx] + 0.114f * Bp[idx];
            v = fmaf(0.5f, d, 0.5f);   // gray((x+1)/2) = (dot(x,w)+1)/2, sum(w)=1
        }
        sA[i * GSTRIDE + j] = v;
    }
    __syncthreads();

    // 2) horizontal gaussian: GDIM rows x BDIM cols (blur col j -> global x = ox-1+j)
    for (int l = tid; l < GDIM * BDIM; l += 256) {
        int i = l / BDIM, j = l - i * BDIM;
        const float* g = &sA[i * GSTRIDE + j];
        sH[i * HSTRIDE + j] = w0 * (g[0] + g[4]) + w1 * (g[1] + g[3]) + w2 * g[2];
    }
    __syncthreads();

    // 3) vertical gaussian into sA. blur(i,j) = global (oy-1+i, ox-1+j).
    //    Laplacian SAME zero-pads the BLUR -> mask out-of-image blur to exactly 0.
    for (int l = tid; l < BDIM * BDIM; l += 256) {
        int i = l / BDIM, j = l - i * BDIM;
        const float* h = &sH[i * HSTRIDE + j];
        float v = w0 * (h[0] + h[4 * HSTRIDE])
                + w1 * (h[HSTRIDE] + h[3 * HSTRIDE])
                + w2 * h[2 * HSTRIDE];
        int yy = oy - 1 + i;
        int xx = ox - 1 + j;
        if (yy < 0 || yy >= HH || xx < 0 || xx >= WW) v = 0.0f;
        sA[i * GSTRIDE + j] = v;
    }
    __syncthreads();

    // 4) laplacian + abs -> store edge map (coalesced 128B row segments per warp)
    const int tx = tid & 63;
    const int r0 = tid >> 6;
    float* eout = g_edges + (size_t)img * NPIX + (size_t)b * HH * WW;
    #pragma unroll
    for (int it = 0; it < 16; ++it) {
        int ty = r0 + it * 4;
        const float* bl = &sA[ty * GSTRIDE + tx];   // blur tile origin = (oy-1, ox-1)
        float lap = bl[1]                    // up    (ty-1, tx) -> tile (ty,   tx+1)
                  + bl[2 * GSTRIDE + 1]      // down  (ty+1, tx) -> tile (ty+2, tx+1)
                  + bl[GSTRIDE]              // left
                  + bl[GSTRIDE + 2]          // right
                  - 4.0f * bl[GSTRIDE + 1];  // center
        eout[(oy + ty) * WW + (ox + tx)] = fabsf(lap);
    }
}

// ---------------------------------------------------------------------------
// Kernel 2: sum |e0 - e1| per block (deterministic), float4 grid-stride
// ---------------------------------------------------------------------------
__global__ __launch_bounds__(256)
void diff_reduce_kernel() {
    __shared__ float wsum[8];
    const int tid = threadIdx.x;
    const float4* e0 = (const float4*)g_edges;
    const float4* e1 = (const float4*)(g_edges + NPIX);
    const int n4 = NPIX / 4;   // 2097152

    float s = 0.0f;
    for (int i = blockIdx.x * 256 + tid; i < n4; i += RED_BLOCKS * 256) {
        float4 a = e0[i], c = e1[i];
        s += fabsf(a.x - c.x) + fabsf(a.y - c.y)
           + fabsf(a.z - c.z) + fabsf(a.w - c.w);
    }
    #pragma unroll
    for (int o = 16; o; o >>= 1) s += __shfl_xor_sync(0xffffffffu, s, o);
    if ((tid & 31) == 0) wsum[tid >> 5] = s;
    __syncthreads();
    if (tid == 0) {
        float t = 0.0f;
        #pragma unroll
        for (int k = 0; k < 8; ++k) t += wsum[k];
        g_partials[blockIdx.x] = t;
    }
}

// ---------------------------------------------------------------------------
// Kernel 3: final sum -> mean; also zero any extra output elements (poison hedge)
// ---------------------------------------------------------------------------
__global__ __launch_bounds__(256)
void finalize_kernel(float* __restrict__ out, int out_size) {
    __shared__ float wsum[8];
    const int tid = threadIdx.x;
    float s = 0.0f;
    for (int l = tid; l < RED_BLOCKS; l += 256) s += g_partials[l];
    #pragma unroll
    for (int o = 16; o; o >>= 1) s += __shfl_xor_sync(0xffffffffu, s, o);
    if ((tid & 31) == 0) wsum[tid >> 5] = s;
    __syncthreads();
    if (tid == 0) {
        float t = 0.0f;
        #pragma unroll
        for (int k = 0; k < 8; ++k) t += wsum[k];
        out[0] = t * (1.0f / 8388608.0f);   // mean over B*1*H*W
    }
    for (int l = 1 + tid; l < out_size; l += 256) out[l] = 0.0f;
}

extern "C" void kernel_launch(void* const* d_in, const int* in_sizes, int n_in,
                              void* d_out, int out_size) {
    const float* gen   = (const float*)d_in[0];
    const float* real_ = (const float*)d_in[1];
    dim3 grid(WW / TILE, HH / TILE, 2 * BB);   // (8, 8, 64)
    edge_map_kernel<<<grid, 256>>>(gen, real_);
    diff_reduce_kernel<<<RED_BLOCKS, 256>>>();
    finalize_kernel<<<1, 256>>>((float*)d_out, out_size);
}

// round 5
// speedup vs baseline: 1.9370x; 1.9370x over previous
#include <cuda_runtime.h>

#define HH 512
#define WW 512
#define BB 32
#define HW (HH * WW)
#define NSTRIPS 10          // 56 output cols per strip, 10*56=560 >= 512
#define OUTW 56
#define HS 64               // rows per y-chunk
#define NYC (HH / HS)       // 8
#define NTASKS (BB * NYC * NSTRIPS)   // 2560 warp-tasks
#define NBLOCKS (NTASKS / 8)          // 320 blocks of 8 warps

__device__ float g_partials[NBLOCKS];

// 5-tap gaussian (sigma=1), fp32-normalized (validated in R4: rel_err 9.8e-8)
#define W0 0.054488685f
#define W1 0.244201342f
#define W2 0.402619947f

// Compute horizontal-gaussian pair (cols c0, c0+1) of gray((x+1)/2) at global
// row yy for one image. Gray outside the image (row or cols) is 0 (conv zero-pad).
// Neighbor gray columns come from lane shuffles (lanes own consecutive col pairs).
__device__ __forceinline__ float2 hblur_row(const float* __restrict__ base,
                                            int yy, int c0, bool colok) {
    float ge = 0.0f, go = 0.0f;
    if (colok && (unsigned)yy < (unsigned)HH) {
        int idx = yy * WW + c0;                       // c0 even -> 8B aligned
        float2 r = *(const float2*)(base + idx);
        float2 g = *(const float2*)(base + HW + idx);
        float2 b = *(const float2*)(base + 2 * HW + idx);
        ge = fmaf(0.5f, fmaf(0.299f, r.x, fmaf(0.587f, g.x, 0.114f * b.x)), 0.5f);
        go = fmaf(0.5f, fmaf(0.299f, r.y, fmaf(0.587f, g.y, 0.114f * b.y)), 0.5f);
    }
    const unsigned m = 0xffffffffu;
    float pge = __shfl_up_sync(m, ge, 1);    // gray(c0-2)
    float pgo = __shfl_up_sync(m, go, 1);    // gray(c0-1)
    float nge = __shfl_down_sync(m, ge, 1);  // gray(c0+2)
    float ngo = __shfl_down_sync(m, go, 1);  // gray(c0+3)
    float2 h;
    h.x = fmaf(W0, pge + nge, fmaf(W1, pgo + go, W2 * ge));   // hblur(c0)
    h.y = fmaf(W0, pgo + ngo, fmaf(W1, ge + nge, W2 * go));   // hblur(c0+1)
    return h;
}

// Vertical 5-tap over the rolling hblur window (rows r-2..r+2 in h[0..4])
__device__ __forceinline__ float2 vblur5(const float2 h[5]) {
    float2 v;
    v.x = fmaf(W0, h[0].x + h[4].x, fmaf(W1, h[1].x + h[3].x, W2 * h[2].x));
    v.y = fmaf(W0, h[0].y + h[4].y, fmaf(W1, h[1].y + h[3].y, W2 * h[2].y));
    return v;
}

__global__ __launch_bounds__(256)
void edge_loss_fused(const float* __restrict__ gen, const float* __restrict__ real_) {
    __shared__ float wsum[8];

    const int tid  = threadIdx.x;
    const int lane = tid & 31;
    const int wid  = tid >> 5;
    const int task = blockIdx.x * 8 + wid;        // 0..2559
    const int s    = task % NSTRIPS;
    const int tb   = task / NSTRIPS;
    const int yc   = tb % NYC;
    const int b    = tb / NYC;                    // 0..31

    const int  c0     = OUTW * s - 4 + 2 * lane;  // even; lane pair = (c0, c0+1)
    const bool colok  = (unsigned)c0 < (unsigned)WW;
    const int  ybase  = yc * HS;
    const bool outlane = (lane >= 2) && (lane <= 29) && colok;
    const unsigned m = 0xffffffffu;

    const float* A  = gen   + (size_t)b * 3 * HW;
    const float* Bq = real_ + (size_t)b * 3 * HW;

    // --- prologue: hblur window rows [ybase-3 .. ybase+1] for both images ---
    float2 h0[5], h1[5];
    #pragma unroll
    for (int k = 0; k < 5; ++k) {
        h0[k] = hblur_row(A,  ybase - 3 + k, c0, colok);
        h1[k] = hblur_row(Bq, ybase - 3 + k, c0, colok);
    }

    // va = vblur(ybase-1): masked 0 outside image (lap zero-pads the BLUR)
    float2 va0 = vblur5(h0), va1 = vblur5(h1);
    if (!(colok && (unsigned)(ybase - 1) < (unsigned)HH)) {
        va0.x = va0.y = va1.x = va1.y = 0.0f;
    }

    // advance window to rows [ybase-2 .. ybase+2]; vb = vblur(ybase)
    #pragma unroll
    for (int k = 0; k < 4; ++k) { h0[k] = h0[k + 1]; h1[k] = h1[k + 1]; }
    h0[4] = hblur_row(A,  ybase + 2, c0, colok);
    h1[4] = hblur_row(Bq, ybase + 2, c0, colok);
    float2 vb0 = vblur5(h0), vb1 = vblur5(h1);
    if (!colok) { vb0.x = vb0.y = vb1.x = vb1.y = 0.0f; }   // ybase always in image

    float acc = 0.0f;

    for (int t = 0; t < HS; ++t) {
        // load hblur row ybase+3+t; vc = vblur(ybase+1+t)
        #pragma unroll
        for (int k = 0; k < 4; ++k) { h0[k] = h0[k + 1]; h1[k] = h1[k + 1]; }
        h0[4] = hblur_row(A,  ybase + 3 + t, c0, colok);
        h1[4] = hblur_row(Bq, ybase + 3 + t, c0, colok);
        float2 vc0 = vblur5(h0), vc1 = vblur5(h1);
        if (!(colok && (unsigned)(ybase + 1 + t) < (unsigned)HH)) {
            vc0.x = vc0.y = vc1.x = vc1.y = 0.0f;
        }

        // laplacian at output row y = ybase + t (cross: va/vc vertical, shuffles horizontal)
        float pv0 = __shfl_up_sync(m, vb0.y, 1);    // v(y, c0-1) img0
        float nv0 = __shfl_down_sync(m, vb0.x, 1);  // v(y, c0+2) img0
        float pv1 = __shfl_up_sync(m, vb1.y, 1);
        float nv1 = __shfl_down_sync(m, vb1.x, 1);

        float l0e = va0.x + vc0.x + pv0   + vb0.y - 4.0f * vb0.x;
        float l0o = va0.y + vc0.y + vb0.x + nv0   - 4.0f * vb0.y;
        float l1e = va1.x + vc1.x + pv1   + vb1.y - 4.0f * vb1.x;
        float l1o = va1.y + vc1.y + vb1.x + nv1   - 4.0f * vb1.y;

        if (outlane) {
            acc += fabsf(fabsf(l0e) - fabsf(l1e)) + fabsf(fabsf(l0o) - fabsf(l1o));
        }

        va0 = vb0; va1 = vb1;
        vb0 = vc0; vb1 = vc1;
    }

    // --- deterministic block reduction ---
    #pragma unroll
    for (int o = 16; o; o >>= 1) acc += __shfl_xor_sync(m, acc, o);
    if (lane == 0) wsum[wid] = acc;
    __syncthreads();
    if (tid == 0) {
        float t = 0.0f;
        #pragma unroll
        for (int k = 0; k < 8; ++k) t += wsum[k];
        g_partials[blockIdx.x] = t;
    }
}

__global__ __launch_bounds__(256)
void finalize_kernel(float* __restrict__ out, int out_size) {
    __shared__ float wsum[8];
    const int tid = threadIdx.x;
    float s = 0.0f;
    for (int l = tid; l < NBLOCKS; l += 256) s += g_partials[l];
    #pragma unroll
    for (int o = 16; o; o >>= 1) s += __shfl_xor_sync(0xffffffffu, s, o);
    if ((tid & 31) == 0) wsum[tid >> 5] = s;
    __syncthreads();
    if (tid == 0) {
        float t = 0.0f;
        #pragma unroll
        for (int k = 0; k < 8; ++k) t += wsum[k];
        out[0] = t * (1.0f / 8388608.0f);   // mean over B*1*H*W
    }
    for (int l = 1 + tid; l < out_size; l += 256) out[l] = 0.0f;
}

extern "C" void kernel_launch(void* const* d_in, const int* in_sizes, int n_in,
                              void* d_out, int out_size) {
    const float* gen   = (const float*)d_in[0];
    const float* real_ = (const float*)d_in[1];
    edge_loss_fused<<<NBLOCKS, 256>>>(gen, real_);
    finalize_kernel<<<1, 256>>>((float*)d_out, out_size);
}